// round 2
// baseline (speedup 1.0000x reference)
#include <cuda_runtime.h>
#include <math.h>

#define D_MODEL   1024
#define NUM_HEADS 16
#define HEAD_DIM  64
#define MAX_SEQ   5000
#define BATCH     2
#define SEQ       2048
#define NROWS     (BATCH * SEQ)        // 4096
#define BHN       (BATCH * NUM_HEADS)  // 32

// ---------------- scratch (static device arrays are allowed) -----------------
__device__ float g_xp [NROWS * D_MODEL];            // x + mixed PE      16 MB
__device__ float g_q  [BHN * SEQ * HEAD_DIM];       // [bh][s][d]        16 MB
__device__ float g_k  [BHN * SEQ * HEAD_DIM];
__device__ float g_v  [BHN * SEQ * HEAD_DIM];
__device__ float g_att[NROWS * D_MODEL];            // [b][s][h*64+d]    16 MB

// ---------------- kernel 1: x + alpha*sinusoid + (1-alpha)*rel ---------------
__global__ void __launch_bounds__(256) pe_add_kernel(
    const float* __restrict__ x, const float* __restrict__ rel,
    const float* __restrict__ alpha_p)
{
    const int row = blockIdx.x;          // 0..4095  (b*SEQ + s)
    const int s   = row & (SEQ - 1);
    const float alpha = *alpha_p;
    const float omal  = 1.0f - alpha;
    // matches jax: div = exp(arange(0,D,2) * (-log(10000)/D)) in fp32
    const float pec = (float)(-9.210340371976184 / 1024.0);
    const float* rrow = rel + (size_t)(MAX_SEQ - SEQ + s) * D_MODEL;
    const float* xrow = x   + (size_t)row * D_MODEL;
    float*       orow = g_xp + (size_t)row * D_MODEL;

    for (int p = threadIdx.x; p < D_MODEL / 2; p += blockDim.x) {
        float dv  = expf((float)(2 * p) * pec);
        float ang = (float)s * dv;
        float sa, ca;
        sincosf(ang, &sa, &ca);
        int i0 = 2 * p;
        orow[i0]     = xrow[i0]     + alpha * sa + omal * rrow[i0];
        orow[i0 + 1] = xrow[i0 + 1] + alpha * ca + omal * rrow[i0 + 1];
    }
}

// ---------------- fp32 SIMT GEMM core: 128x128x16 tile, 8x8/thread -----------
#define GBM 128
#define GBN 128
#define GBK 16

// y[m][n] = sum_k A[m][k] * W[n][k]   (W row-major [n][k], i.e. x @ W^T)
// As/Bs stored transposed: As[k][m], Bs[k][n] -> float4 fragment loads.

__device__ __forceinline__ void gemm_tile_compute(
    const float* __restrict__ A, const float* __restrict__ W,
    int m0, int n0, int ty, int tx, int tid,
    float (*As)[GBM], float (*Bs)[GBN], float acc[8][8])
{
    for (int k0 = 0; k0 < D_MODEL; k0 += GBK) {
        // load A tile (128x16) and W tile (128x16): 512 float4 each, 2/thread
        #pragma unroll
        for (int it = 0; it < 2; it++) {
            int idx = tid + it * 256;
            int row = idx >> 2;
            int kq  = (idx & 3) << 2;
            float4 va = *(const float4*)&A[(size_t)(m0 + row) * D_MODEL + k0 + kq];
            As[kq + 0][row] = va.x; As[kq + 1][row] = va.y;
            As[kq + 2][row] = va.z; As[kq + 3][row] = va.w;
            float4 vb = *(const float4*)&W[(size_t)(n0 + row) * D_MODEL + k0 + kq];
            Bs[kq + 0][row] = vb.x; Bs[kq + 1][row] = vb.y;
            Bs[kq + 2][row] = vb.z; Bs[kq + 3][row] = vb.w;
        }
        __syncthreads();
        #pragma unroll
        for (int kk = 0; kk < GBK; kk++) {
            float a[8], b[8];
            *(float4*)&a[0] = *(const float4*)&As[kk][ty * 8];
            *(float4*)&a[4] = *(const float4*)&As[kk][ty * 8 + 4];
            *(float4*)&b[0] = *(const float4*)&Bs[kk][tx * 8];
            *(float4*)&b[4] = *(const float4*)&Bs[kk][tx * 8 + 4];
            #pragma unroll
            for (int i = 0; i < 8; i++)
                #pragma unroll
                for (int j = 0; j < 8; j++)
                    acc[i][j] = fmaf(a[i], b[j], acc[i][j]);
        }
        __syncthreads();
    }
}

// ---- QKV: z selects weight; store into [b*H+h][s][d] layout -----------------
__global__ void __launch_bounds__(256) gemm_qkv_kernel(
    const float* __restrict__ Wq, const float* __restrict__ bq,
    const float* __restrict__ Wk, const float* __restrict__ bk,
    const float* __restrict__ Wv, const float* __restrict__ bv)
{
    __shared__ float As[GBK][GBM];
    __shared__ float Bs[GBK][GBN];
    const int z = blockIdx.z;
    const float* W    = (z == 0) ? Wq : (z == 1) ? Wk : Wv;
    const float* bias = (z == 0) ? bq : (z == 1) ? bk : bv;
    float* dst        = (z == 0) ? g_q : (z == 1) ? g_k : g_v;

    const int m0 = blockIdx.y * GBM;
    const int n0 = blockIdx.x * GBN;
    const int tid = threadIdx.x;
    const int ty = tid >> 4, tx = tid & 15;

    float acc[8][8] = {};
    gemm_tile_compute(g_xp, W, m0, n0, ty, tx, tid, As, Bs, acc);

    #pragma unroll
    for (int i = 0; i < 8; i++) {
        int m  = m0 + ty * 8 + i;
        int b_ = m >> 11;               // /SEQ
        int s_ = m & (SEQ - 1);
        #pragma unroll
        for (int j = 0; j < 8; j++) {
            int n = n0 + tx * 8 + j;
            int h = n >> 6;
            int d = n & 63;
            dst[((size_t)(b_ * NUM_HEADS + h) * SEQ + s_) * HEAD_DIM + d] =
                acc[i][j] + bias[n];
        }
    }
}

// ---- output projection: plain row-major store -------------------------------
__global__ void __launch_bounds__(256) gemm_out_kernel(
    const float* __restrict__ Wo, const float* __restrict__ bo,
    float* __restrict__ out)
{
    __shared__ float As[GBK][GBM];
    __shared__ float Bs[GBK][GBN];
    const int m0 = blockIdx.y * GBM;
    const int n0 = blockIdx.x * GBN;
    const int tid = threadIdx.x;
    const int ty = tid >> 4, tx = tid & 15;

    float acc[8][8] = {};
    gemm_tile_compute(g_att, Wo, m0, n0, ty, tx, tid, As, Bs, acc);

    #pragma unroll
    for (int i = 0; i < 8; i++) {
        int m = m0 + ty * 8 + i;
        #pragma unroll
        for (int j = 0; j < 8; j++) {
            int n = n0 + tx * 8 + j;
            out[(size_t)m * D_MODEL + n] = acc[i][j] + bo[n];
        }
    }
}

// ---------------- kernel 3: flash attention, fp32 ----------------------------
// grid (S/64, BHN), 256 threads = 16x16, each thread owns 4x4 of a 64x64 tile.
__device__ __forceinline__ float rmax16(float v) {
    #pragma unroll
    for (int off = 8; off >= 1; off >>= 1)
        v = fmaxf(v, __shfl_xor_sync(0xffffffffu, v, off));
    return v;
}
__device__ __forceinline__ float rsum16(float v) {
    #pragma unroll
    for (int off = 8; off >= 1; off >>= 1)
        v += __shfl_xor_sync(0xffffffffu, v, off);
    return v;
}

__global__ void __launch_bounds__(256) flash_kernel()
{
    __shared__ float Qt[64][64];    // Q^T : [d][i]
    __shared__ float KtPs[64][64];  // K^T : [d][j], reused as P : [i][j]
    __shared__ float Vs[64][64];    // V   : [j][d]

    const int bh = blockIdx.y;
    const int qt = blockIdx.x;
    const int tid = threadIdx.x;
    const int ty = tid >> 4, tx = tid & 15;

    const float* Qb = g_q + ((size_t)bh * SEQ + qt * 64) * HEAD_DIM;
    const float* Kb = g_k + (size_t)bh * SEQ * HEAD_DIM;
    const float* Vb = g_v + (size_t)bh * SEQ * HEAD_DIM;

    // load Q transposed
    #pragma unroll
    for (int it = 0; it < 4; it++) {
        int idx = tid + it * 256;
        int row = idx & 63;
        int dq  = (idx >> 6) * 4;
        float4 v = *(const float4*)&Qb[row * 64 + dq];
        Qt[dq + 0][row] = v.x; Qt[dq + 1][row] = v.y;
        Qt[dq + 2][row] = v.z; Qt[dq + 3][row] = v.w;
    }

    float o[4][4];
    float mst[4], lst[4];
    #pragma unroll
    for (int r = 0; r < 4; r++) {
        mst[r] = -INFINITY; lst[r] = 0.0f;
        #pragma unroll
        for (int c = 0; c < 4; c++) o[r][c] = 0.0f;
    }

    for (int kt = 0; kt < SEQ / 64; kt++) {
        __syncthreads();   // prior-iter smem reads done (also publishes Qt on iter 0)
        const float* Kp = Kb + (size_t)kt * 64 * 64;
        const float* Vp = Vb + (size_t)kt * 64 * 64;
        #pragma unroll
        for (int it = 0; it < 4; it++) {
            int idx = tid + it * 256;
            int row = idx & 63;
            int dq  = (idx >> 6) * 4;
            float4 kv = *(const float4*)&Kp[row * 64 + dq];
            KtPs[dq + 0][row] = kv.x; KtPs[dq + 1][row] = kv.y;
            KtPs[dq + 2][row] = kv.z; KtPs[dq + 3][row] = kv.w;
            int row2 = idx >> 4;
            int dq2  = (idx & 15) * 4;
            *(float4*)&Vs[row2][dq2] = *(const float4*)&Vp[row2 * 64 + dq2];
        }
        __syncthreads();

        // S = Q K^T  (64x64, K-dim 64)
        float sacc[4][4] = {};
        #pragma unroll 8
        for (int d = 0; d < 64; d++) {
            float4 qa = *(const float4*)&Qt[d][ty * 4];
            float4 kb = *(const float4*)&KtPs[d][tx * 4];
            float av[4] = {qa.x, qa.y, qa.z, qa.w};
            float bv[4] = {kb.x, kb.y, kb.z, kb.w};
            #pragma unroll
            for (int r = 0; r < 4; r++)
                #pragma unroll
                for (int c = 0; c < 4; c++)
                    sacc[r][c] = fmaf(av[r], bv[c], sacc[r][c]);
        }
        __syncthreads();   // KtPs reads done -> safe to overwrite with P

        // online softmax (scale = 1/sqrt(D_MODEL) = 1/32, per reference)
        float fac[4];
        #pragma unroll
        for (int r = 0; r < 4; r++) {
            float mloc = -INFINITY;
            #pragma unroll
            for (int c = 0; c < 4; c++) {
                sacc[r][c] *= 0.03125f;
                mloc = fmaxf(mloc, sacc[r][c]);
            }
            mloc = rmax16(mloc);
            float mnew = fmaxf(mst[r], mloc);
            fac[r] = expf(mst[r] - mnew);      // expf(-inf)=0 on iter 0
            float sum = 0.0f;
            #pragma unroll
            for (int c = 0; c < 4; c++) {
                float p = expf(sacc[r][c] - mnew);
                sacc[r][c] = p;
                sum += p;
            }
            sum = rsum16(sum);
            lst[r] = lst[r] * fac[r] + sum;
            mst[r] = mnew;
        }
        #pragma unroll
        for (int r = 0; r < 4; r++) {
            *(float4*)&KtPs[ty * 4 + r][tx * 4] =
                make_float4(sacc[r][0], sacc[r][1], sacc[r][2], sacc[r][3]);
            #pragma unroll
            for (int c = 0; c < 4; c++) o[r][c] *= fac[r];
        }
        __syncthreads();   // P visible

        // O += P V  (K-dim 64)
        #pragma unroll 8
        for (int j = 0; j < 64; j++) {
            float4 vv = *(const float4*)&Vs[j][tx * 4];
            float vr[4] = {vv.x, vv.y, vv.z, vv.w};
            float pr[4];
            #pragma unroll
            for (int r = 0; r < 4; r++) pr[r] = KtPs[ty * 4 + r][j];
            #pragma unroll
            for (int r = 0; r < 4; r++)
                #pragma unroll
                for (int c = 0; c < 4; c++)
                    o[r][c] = fmaf(pr[r], vr[c], o[r][c]);
        }
    }

    // epilogue: normalize and write to [b][s][h*64+d]
    const int b_ = bh >> 4;
    const int h  = bh & 15;
    #pragma unroll
    for (int r = 0; r < 4; r++) {
        int srow = qt * 64 + ty * 4 + r;
        float inv = 1.0f / lst[r];
        float4 ov = make_float4(o[r][0] * inv, o[r][1] * inv,
                                o[r][2] * inv, o[r][3] * inv);
        *(float4*)&g_att[((size_t)(b_ * SEQ + srow)) * D_MODEL + h * 64 + tx * 4] = ov;
    }
}

// ---------------- launch -----------------------------------------------------
extern "C" void kernel_launch(void* const* d_in, const int* in_sizes, int n_in,
                              void* d_out, int out_size)
{
    (void)in_sizes; (void)n_in; (void)out_size;
    const float* x     = (const float*)d_in[0];
    const float* rel   = (const float*)d_in[1];
    const float* alpha = (const float*)d_in[2];
    const float* Wq = (const float*)d_in[3];
    const float* bq = (const float*)d_in[4];
    const float* Wk = (const float*)d_in[5];
    const float* bk = (const float*)d_in[6];
    const float* Wv = (const float*)d_in[7];
    const float* bv = (const float*)d_in[8];
    const float* Wo = (const float*)d_in[9];
    const float* bo = (const float*)d_in[10];
    float* out = (float*)d_out;

    pe_add_kernel<<<NROWS, 256>>>(x, rel, alpha);
    gemm_qkv_kernel<<<dim3(D_MODEL / GBN, NROWS / GBM, 3), 256>>>(Wq, bq, Wk, bk, Wv, bv);
    flash_kernel<<<dim3(SEQ / 64, BHN), 256>>>();
    gemm_out_kernel<<<dim3(D_MODEL / GBN, NROWS / GBM), 256>>>(Wo, bo, out);
}

// round 4
// speedup vs baseline: 1.7980x; 1.7980x over previous
#include <cuda_runtime.h>
#include <cuda_bf16.h>
#include <math.h>
#include <stdint.h>

#define D_MODEL   1024
#define NUM_HEADS 16
#define HEAD_DIM  64
#define MAX_SEQ   5000
#define BATCH     2
#define SEQ       2048
#define NROWS     (BATCH * SEQ)        // 4096
#define BHN       (BATCH * NUM_HEADS)  // 32

typedef __nv_bfloat16  bf16;
typedef __nv_bfloat162 bf162;

// ---------------- scratch (static device arrays are allowed) -----------------
__device__ bf16 xp_hi [NROWS * D_MODEL];
__device__ bf16 xp_lo [NROWS * D_MODEL];
__device__ bf16 w4_hi [4 * D_MODEL * D_MODEL];   // Wq,Wk,Wv,Wo concatenated
__device__ bf16 w4_lo [4 * D_MODEL * D_MODEL];
__device__ bf16 q_hi  [BHN * SEQ * HEAD_DIM];
__device__ bf16 q_lo  [BHN * SEQ * HEAD_DIM];
__device__ bf16 k_hi  [BHN * SEQ * HEAD_DIM];
__device__ bf16 k_lo  [BHN * SEQ * HEAD_DIM];
__device__ bf16 v_hi  [BHN * SEQ * HEAD_DIM];
__device__ bf16 v_lo  [BHN * SEQ * HEAD_DIM];
__device__ bf16 att_hi[NROWS * D_MODEL];
__device__ bf16 att_lo[NROWS * D_MODEL];

// ---------------- helpers ----------------------------------------------------
__device__ __forceinline__ void mma_bf16(float c[4], const uint32_t a[4],
                                         const uint32_t b[2])
{
    asm volatile(
        "mma.sync.aligned.m16n8k16.row.col.f32.bf16.bf16.f32 "
        "{%0,%1,%2,%3}, {%4,%5,%6,%7}, {%8,%9}, {%0,%1,%2,%3};\n"
        : "+f"(c[0]), "+f"(c[1]), "+f"(c[2]), "+f"(c[3])
        : "r"(a[0]), "r"(a[1]), "r"(a[2]), "r"(a[3]), "r"(b[0]), "r"(b[1]));
}

// split two fp32 into packed bf16x2 (hi, lo residual)
__device__ __forceinline__ void split2(float v0, float v1, bf162& hi, bf162& lo)
{
    bf16 h0 = __float2bfloat16(v0);
    bf16 h1 = __float2bfloat16(v1);
    hi = __halves2bfloat162(h0, h1);
    lo = __halves2bfloat162(__float2bfloat16(v0 - __bfloat162float(h0)),
                            __float2bfloat16(v1 - __bfloat162float(h1)));
}

// ---------------- kernel 1: x + alpha*sinusoid + (1-alpha)*rel, split --------
__global__ void __launch_bounds__(256) pe_add_kernel(
    const float* __restrict__ x, const float* __restrict__ rel,
    const float* __restrict__ alpha_p)
{
    const int row = blockIdx.x;          // b*SEQ + s
    const int s   = row & (SEQ - 1);
    const float alpha = *alpha_p;
    const float omal  = 1.0f - alpha;
    const float pec = (float)(-9.210340371976184 / 1024.0);
    const float* rrow = rel + (size_t)(MAX_SEQ - SEQ + s) * D_MODEL;
    const float* xrow = x   + (size_t)row * D_MODEL;
    bf16* oh = xp_hi + (size_t)row * D_MODEL;
    bf16* ol = xp_lo + (size_t)row * D_MODEL;

    for (int p = threadIdx.x; p < D_MODEL / 2; p += blockDim.x) {
        float dv  = expf((float)(2 * p) * pec);
        float ang = (float)s * dv;
        float sa, ca;
        sincosf(ang, &sa, &ca);
        int i0 = 2 * p;
        float v0 = xrow[i0]     + alpha * sa + omal * rrow[i0];
        float v1 = xrow[i0 + 1] + alpha * ca + omal * rrow[i0 + 1];
        bf162 hi, lo;
        split2(v0, v1, hi, lo);
        *(bf162*)&oh[i0] = hi;
        *(bf162*)&ol[i0] = lo;
    }
}

// ---------------- kernel 2: split the 4 weight matrices ----------------------
__global__ void __launch_bounds__(256) wsplit_kernel(
    const float* __restrict__ Wq, const float* __restrict__ Wk,
    const float* __restrict__ Wv, const float* __restrict__ Wo)
{
    size_t idx = ((size_t)blockIdx.x * 256 + threadIdx.x) * 4;   // 0..4M
    int wsel = (int)(idx >> 20);
    size_t local = idx & ((1u << 20) - 1);
    const float* W = (wsel == 0) ? Wq : (wsel == 1) ? Wk : (wsel == 2) ? Wv : Wo;
    float4 v = *(const float4*)&W[local];
    bf162 h0, l0, h1, l1;
    split2(v.x, v.y, h0, l0);
    split2(v.z, v.w, h1, l1);
    *(bf162*)&w4_hi[idx]     = h0;
    *(bf162*)&w4_hi[idx + 2] = h1;
    *(bf162*)&w4_lo[idx]     = l0;
    *(bf162*)&w4_lo[idx + 2] = l1;
}

// ---------------- 3-split bf16 tensor-core GEMM core -------------------------
// C[128x128] = A[128x1024] @ W^T, tiles BK=32, 8 warps (wm 2 x wn 4),
// warp tile 64x32 -> 4x4 mma tiles of m16n8k16.
#define GSTR 40   // smem row stride (bf16 elements), conflict-free

__device__ __forceinline__ void gemm3_compute(
    const bf16* __restrict__ Ah, const bf16* __restrict__ Al,
    const bf16* __restrict__ Wh, const bf16* __restrict__ Wl,
    int m0, int n0, int tid,
    bf16* Ash, bf16* Asl, bf16* Bsh, bf16* Bsl,
    float acc[4][4][4])
{
    const int lane = tid & 31;
    const int w    = tid >> 5;
    const int wm   = w >> 2;       // 0..1
    const int wn   = w & 3;        // 0..3
    const int gid  = lane >> 2;    // 0..7
    const int tig  = lane & 3;     // 0..3

    for (int k0 = 0; k0 < D_MODEL; k0 += 32) {
        __syncthreads();
        #pragma unroll
        for (int it = 0; it < 2; it++) {
            int lin = tid + it * 256;
            int row = lin >> 2;
            int quad = lin & 3;
            size_t ga = (size_t)(m0 + row) * D_MODEL + k0 + quad * 8;
            size_t gb = (size_t)(n0 + row) * D_MODEL + k0 + quad * 8;
            int sm = row * GSTR + quad * 8;
            *(uint4*)&Ash[sm] = *(const uint4*)&Ah[ga];
            *(uint4*)&Asl[sm] = *(const uint4*)&Al[ga];
            *(uint4*)&Bsh[sm] = *(const uint4*)&Wh[gb];
            *(uint4*)&Bsl[sm] = *(const uint4*)&Wl[gb];
        }
        __syncthreads();
        #pragma unroll
        for (int ks = 0; ks < 2; ks++) {
            uint32_t ah[4][4], al[4][4], bh[4][2], bl[4][2];
            #pragma unroll
            for (int mt = 0; mt < 4; mt++) {
                int base = (wm * 64 + mt * 16 + gid) * GSTR + ks * 16 + tig * 2;
                ah[mt][0] = *(const uint32_t*)&Ash[base];
                ah[mt][1] = *(const uint32_t*)&Ash[base + 8 * GSTR];
                ah[mt][2] = *(const uint32_t*)&Ash[base + 8];
                ah[mt][3] = *(const uint32_t*)&Ash[base + 8 * GSTR + 8];
                al[mt][0] = *(const uint32_t*)&Asl[base];
                al[mt][1] = *(const uint32_t*)&Asl[base + 8 * GSTR];
                al[mt][2] = *(const uint32_t*)&Asl[base + 8];
                al[mt][3] = *(const uint32_t*)&Asl[base + 8 * GSTR + 8];
            }
            #pragma unroll
            for (int nt = 0; nt < 4; nt++) {
                int base = (wn * 32 + nt * 8 + gid) * GSTR + ks * 16 + tig * 2;
                bh[nt][0] = *(const uint32_t*)&Bsh[base];
                bh[nt][1] = *(const uint32_t*)&Bsh[base + 8];
                bl[nt][0] = *(const uint32_t*)&Bsl[base];
                bl[nt][1] = *(const uint32_t*)&Bsl[base + 8];
            }
            #pragma unroll
            for (int mt = 0; mt < 4; mt++)
                #pragma unroll
                for (int nt = 0; nt < 4; nt++) {
                    mma_bf16(acc[mt][nt], ah[mt], bh[nt]);
                    mma_bf16(acc[mt][nt], ah[mt], bl[nt]);
                    mma_bf16(acc[mt][nt], al[mt], bh[nt]);
                }
        }
    }
}

// ---- QKV GEMM: z = 0/1/2 -> q/k/v, split-stored in [bh][s][d] ---------------
__global__ void __launch_bounds__(256) gemm_qkv_kernel(
    const float* __restrict__ bq, const float* __restrict__ bk,
    const float* __restrict__ bv)
{
    __shared__ bf16 Ash[128 * GSTR], Asl[128 * GSTR];
    __shared__ bf16 Bsh[128 * GSTR], Bsl[128 * GSTR];

    const int z  = blockIdx.z;
    const float* bias = (z == 0) ? bq : (z == 1) ? bk : bv;
    bf16* dh = (z == 0) ? q_hi : (z == 1) ? k_hi : v_hi;
    bf16* dl = (z == 0) ? q_lo : (z == 1) ? k_lo : v_lo;
    const bf16* Wh = w4_hi + (size_t)z * D_MODEL * D_MODEL;
    const bf16* Wl = w4_lo + (size_t)z * D_MODEL * D_MODEL;

    const int m0 = blockIdx.y * 128;
    const int n0 = blockIdx.x * 128;
    const int tid = threadIdx.x;
    const int lane = tid & 31, w = tid >> 5;
    const int wm = w >> 2, wn = w & 3, gid = lane >> 2, tig = lane & 3;

    float acc[4][4][4] = {};
    gemm3_compute(xp_hi, xp_lo, Wh, Wl, m0, n0, tid, Ash, Asl, Bsh, Bsl, acc);

    #pragma unroll
    for (int mt = 0; mt < 4; mt++) {
        #pragma unroll
        for (int nt = 0; nt < 4; nt++) {
            int n = n0 + wn * 32 + nt * 8 + tig * 2;
            int h = n >> 6, d = n & 63;
            float bb0 = bias[n], bb1 = bias[n + 1];
            #pragma unroll
            for (int half = 0; half < 2; half++) {
                int m  = m0 + wm * 64 + mt * 16 + gid + half * 8;
                int b_ = m >> 11;
                int s_ = m & (SEQ - 1);
                float v0 = acc[mt][nt][half * 2]     + bb0;
                float v1 = acc[mt][nt][half * 2 + 1] + bb1;
                bf162 hi, lo;
                split2(v0, v1, hi, lo);
                size_t dst = ((size_t)(b_ * NUM_HEADS + h) * SEQ + s_) * HEAD_DIM + d;
                *(bf162*)&dh[dst] = hi;
                *(bf162*)&dl[dst] = lo;
            }
        }
    }
}

// ---- output projection ------------------------------------------------------
__global__ void __launch_bounds__(256) gemm_out_kernel(
    const float* __restrict__ bo, float* __restrict__ out)
{
    __shared__ bf16 Ash[128 * GSTR], Asl[128 * GSTR];
    __shared__ bf16 Bsh[128 * GSTR], Bsl[128 * GSTR];

    const bf16* Wh = w4_hi + (size_t)3 * D_MODEL * D_MODEL;
    const bf16* Wl = w4_lo + (size_t)3 * D_MODEL * D_MODEL;

    const int m0 = blockIdx.y * 128;
    const int n0 = blockIdx.x * 128;
    const int tid = threadIdx.x;
    const int lane = tid & 31, w = tid >> 5;
    const int wm = w >> 2, wn = w & 3, gid = lane >> 2, tig = lane & 3;

    float acc[4][4][4] = {};
    gemm3_compute(att_hi, att_lo, Wh, Wl, m0, n0, tid, Ash, Asl, Bsh, Bsl, acc);

    #pragma unroll
    for (int mt = 0; mt < 4; mt++) {
        #pragma unroll
        for (int nt = 0; nt < 4; nt++) {
            int n = n0 + wn * 32 + nt * 8 + tig * 2;
            float bb0 = bo[n], bb1 = bo[n + 1];
            #pragma unroll
            for (int half = 0; half < 2; half++) {
                int m = m0 + wm * 64 + mt * 16 + gid + half * 8;
                out[(size_t)m * D_MODEL + n]     = acc[mt][nt][half * 2]     + bb0;
                out[(size_t)m * D_MODEL + n + 1] = acc[mt][nt][half * 2 + 1] + bb1;
            }
        }
    }
}

// ---------------- kernel 3: flash attention, tensor-core 3-split -------------
// grid (SEQ/64, BHN), 256 threads = 8 warps; wm = w>>1 (rows), wn = w&1.
// S chunk: 64(q) x 32(k); O tile per warp: 16 rows x 32 d-cols.
#define FSTR_Q 72    // Q/K smem stride
#define FSTR_P 40    // P/Vt smem stride

__global__ void __launch_bounds__(256) flash_kernel()
{
    __shared__ bf16 QPh[64 * FSTR_Q], QPl[64 * FSTR_Q];   // Q then reused as P
    __shared__ bf16 Ksh[32 * FSTR_Q], Ksl[32 * FSTR_Q];
    __shared__ bf16 Vth[64 * FSTR_P], Vtl[64 * FSTR_P];   // V^T : [d][j]
    __shared__ float redmax[2][64], redsum[2][64];

    const int bh = blockIdx.y;
    const int qt = blockIdx.x;
    const int tid = threadIdx.x;
    const int lane = tid & 31, w = tid >> 5;
    const int wm = w >> 1;     // 0..3 : 16-row band
    const int wn = w & 1;      // 0..1
    const int gid = lane >> 2, tig = lane & 3;

    const size_t qbase = ((size_t)bh * SEQ + qt * 64) * HEAD_DIM;
    const size_t kvb   = (size_t)bh * SEQ * HEAD_DIM;

    // ---- load Q tile into smem (stride FSTR_Q), then frags to registers ----
    #pragma unroll
    for (int it = 0; it < 2; it++) {
        int lin = tid + it * 256;
        int row = lin >> 3, quad = lin & 7;
        int sm = row * FSTR_Q + quad * 8;
        *(uint4*)&QPh[sm] = *(const uint4*)&q_hi[qbase + (size_t)row * 64 + quad * 8];
        *(uint4*)&QPl[sm] = *(const uint4*)&q_lo[qbase + (size_t)row * 64 + quad * 8];
    }
    __syncthreads();

    uint32_t qfh[4][4], qfl[4][4];
    #pragma unroll
    for (int ks = 0; ks < 4; ks++) {
        int base = (wm * 16 + gid) * FSTR_Q + ks * 16 + tig * 2;
        qfh[ks][0] = *(const uint32_t*)&QPh[base];
        qfh[ks][1] = *(const uint32_t*)&QPh[base + 8 * FSTR_Q];
        qfh[ks][2] = *(const uint32_t*)&QPh[base + 8];
        qfh[ks][3] = *(const uint32_t*)&QPh[base + 8 * FSTR_Q + 8];
        qfl[ks][0] = *(const uint32_t*)&QPl[base];
        qfl[ks][1] = *(const uint32_t*)&QPl[base + 8 * FSTR_Q];
        qfl[ks][2] = *(const uint32_t*)&QPl[base + 8];
        qfl[ks][3] = *(const uint32_t*)&QPl[base + 8 * FSTR_Q + 8];
    }

    float oacc[4][4] = {};
    float mst0 = -INFINITY, mst1 = -INFINITY, lst0 = 0.0f, lst1 = 0.0f;
    const int r0 = wm * 16 + gid;
    const int r1 = r0 + 8;

    for (int kt = 0; kt < SEQ / 32; kt++) {
        const int j0 = kt * 32;
        __syncthreads();   // prior-iter Ps/Vt/Ks reads done (and Q frag reads, iter 0)

        // K tile [j=32][d=64] direct; V tile transposed -> Vt[d][j]
        {
            int row = tid >> 3, quad = tid & 7;
            size_t g = kvb + (size_t)(j0 + row) * 64 + quad * 8;
            int sm = row * FSTR_Q + quad * 8;
            *(uint4*)&Ksh[sm] = *(const uint4*)&k_hi[g];
            *(uint4*)&Ksl[sm] = *(const uint4*)&k_lo[g];
        }
        #pragma unroll
        for (int it = 0; it < 4; it++) {
            int lin = tid + it * 256;
            int j = lin >> 5;
            int dp = (lin & 31) * 2;
            size_t g = kvb + (size_t)(j0 + j) * 64 + dp;
            uint32_t uh = *(const uint32_t*)&v_hi[g];
            uint32_t ul = *(const uint32_t*)&v_lo[g];
            bf162 bhh = *(bf162*)&uh;
            bf162 bll = *(bf162*)&ul;
            Vth[(dp)     * FSTR_P + j] = __low2bfloat16(bhh);
            Vth[(dp + 1) * FSTR_P + j] = __high2bfloat16(bhh);
            Vtl[(dp)     * FSTR_P + j] = __low2bfloat16(bll);
            Vtl[(dp + 1) * FSTR_P + j] = __high2bfloat16(bll);
        }
        __syncthreads();

        // ---- S = Q @ K^T (3-split) ----
        float sacc[2][4] = {};
        #pragma unroll
        for (int ks = 0; ks < 4; ks++) {
            #pragma unroll
            for (int nt = 0; nt < 2; nt++) {
                int base = (wn * 16 + nt * 8 + gid) * FSTR_Q + ks * 16 + tig * 2;
                uint32_t kbh[2], kbl[2];
                kbh[0] = *(const uint32_t*)&Ksh[base];
                kbh[1] = *(const uint32_t*)&Ksh[base + 8];
                kbl[0] = *(const uint32_t*)&Ksl[base];
                kbl[1] = *(const uint32_t*)&Ksl[base + 8];
                mma_bf16(sacc[nt], qfh[ks], kbh);
                mma_bf16(sacc[nt], qfh[ks], kbl);
                mma_bf16(sacc[nt], qfl[ks], kbh);
            }
        }

        // ---- online softmax ----
        #pragma unroll
        for (int nt = 0; nt < 2; nt++)
            #pragma unroll
            for (int c = 0; c < 4; c++) sacc[nt][c] *= 0.03125f;

        float m0 = fmaxf(fmaxf(sacc[0][0], sacc[0][1]), fmaxf(sacc[1][0], sacc[1][1]));
        float m1 = fmaxf(fmaxf(sacc[0][2], sacc[0][3]), fmaxf(sacc[1][2], sacc[1][3]));
        #pragma unroll
        for (int off = 1; off <= 2; off <<= 1) {
            m0 = fmaxf(m0, __shfl_xor_sync(0xffffffffu, m0, off));
            m1 = fmaxf(m1, __shfl_xor_sync(0xffffffffu, m1, off));
        }
        if (tig == 0) { redmax[wn][r0] = m0; redmax[wn][r1] = m1; }
        __syncthreads();
        float mc0 = fmaxf(redmax[0][r0], redmax[1][r0]);
        float mc1 = fmaxf(redmax[0][r1], redmax[1][r1]);
        float mn0 = fmaxf(mst0, mc0);
        float mn1 = fmaxf(mst1, mc1);
        float fac0 = expf(mst0 - mn0);
        float fac1 = expf(mst1 - mn1);

        float sum0 = 0.0f, sum1 = 0.0f;
        #pragma unroll
        for (int nt = 0; nt < 2; nt++) {
            float p00 = expf(sacc[nt][0] - mn0);
            float p01 = expf(sacc[nt][1] - mn0);
            float p10 = expf(sacc[nt][2] - mn1);
            float p11 = expf(sacc[nt][3] - mn1);
            sum0 += p00 + p01;
            sum1 += p10 + p11;
            int cb = wn * 16 + nt * 8 + tig * 2;
            bf162 hi, lo;
            split2(p00, p01, hi, lo);
            *(bf162*)&QPh[r0 * FSTR_P + cb] = hi;
            *(bf162*)&QPl[r0 * FSTR_P + cb] = lo;
            split2(p10, p11, hi, lo);
            *(bf162*)&QPh[r1 * FSTR_P + cb] = hi;
            *(bf162*)&QPl[r1 * FSTR_P + cb] = lo;
        }
        #pragma unroll
        for (int off = 1; off <= 2; off <<= 1) {
            sum0 += __shfl_xor_sync(0xffffffffu, sum0, off);
            sum1 += __shfl_xor_sync(0xffffffffu, sum1, off);
        }
        if (tig == 0) { redsum[wn][r0] = sum0; redsum[wn][r1] = sum1; }

        // rescale O by fac
        #pragma unroll
        for (int nt = 0; nt < 4; nt++) {
            oacc[nt][0] *= fac0; oacc[nt][1] *= fac0;
            oacc[nt][2] *= fac1; oacc[nt][3] *= fac1;
        }
        mst0 = mn0; mst1 = mn1;
        __syncthreads();
        lst0 = lst0 * fac0 + redsum[0][r0] + redsum[1][r0];
        lst1 = lst1 * fac1 + redsum[0][r1] + redsum[1][r1];

        // ---- O += P @ V (3-split) ----
        #pragma unroll
        for (int ks = 0; ks < 2; ks++) {
            uint32_t ph[4], pl[4];
            int abase = (wm * 16 + gid) * FSTR_P + ks * 16 + tig * 2;
            ph[0] = *(const uint32_t*)&QPh[abase];
            ph[1] = *(const uint32_t*)&QPh[abase + 8 * FSTR_P];
            ph[2] = *(const uint32_t*)&QPh[abase + 8];
            ph[3] = *(const uint32_t*)&QPh[abase + 8 * FSTR_P + 8];
            pl[0] = *(const uint32_t*)&QPl[abase];
            pl[1] = *(const uint32_t*)&QPl[abase + 8 * FSTR_P];
            pl[2] = *(const uint32_t*)&QPl[abase + 8];
            pl[3] = *(const uint32_t*)&QPl[abase + 8 * FSTR_P + 8];
            #pragma unroll
            for (int nt = 0; nt < 4; nt++) {
                int bbase = (wn * 32 + nt * 8 + gid) * FSTR_P + ks * 16 + tig * 2;
                uint32_t vbh[2], vbl[2];
                vbh[0] = *(const uint32_t*)&Vth[bbase];
                vbh[1] = *(const uint32_t*)&Vth[bbase + 8];
                vbl[0] = *(const uint32_t*)&Vtl[bbase];
                vbl[1] = *(const uint32_t*)&Vtl[bbase + 8];
                mma_bf16(oacc[nt], ph, vbh);
                mma_bf16(oacc[nt], ph, vbl);
                mma_bf16(oacc[nt], pl, vbh);
            }
        }
    }

    // ---- epilogue: normalize, split-store into att[b][s][h*64+d] ------------
    const int b_ = bh >> 4;
    const int h  = bh & 15;
    float inv0 = 1.0f / lst0;
    float inv1 = 1.0f / lst1;
    #pragma unroll
    for (int nt = 0; nt < 4; nt++) {
        int col = h * 64 + wn * 32 + nt * 8 + tig * 2;
        size_t a0 = ((size_t)b_ * SEQ + qt * 64 + r0) * D_MODEL + col;
        size_t a1 = ((size_t)b_ * SEQ + qt * 64 + r1) * D_MODEL + col;
        bf162 hi, lo;
        split2(oacc[nt][0] * inv0, oacc[nt][1] * inv0, hi, lo);
        *(bf162*)&att_hi[a0] = hi;
        *(bf162*)&att_lo[a0] = lo;
        split2(oacc[nt][2] * inv1, oacc[nt][3] * inv1, hi, lo);
        *(bf162*)&att_hi[a1] = hi;
        *(bf162*)&att_lo[a1] = lo;
    }
}

// ---------------- launch -----------------------------------------------------
extern "C" void kernel_launch(void* const* d_in, const int* in_sizes, int n_in,
                              void* d_out, int out_size)
{
    (void)in_sizes; (void)n_in; (void)out_size;
    const float* x     = (const float*)d_in[0];
    const float* rel   = (const float*)d_in[1];
    const float* alpha = (const float*)d_in[2];
    const float* Wq = (const float*)d_in[3];
    const float* bq = (const float*)d_in[4];
    const float* Wk = (const float*)d_in[5];
    const float* bk = (const float*)d_in[6];
    const float* Wv = (const float*)d_in[7];
    const float* bv = (const float*)d_in[8];
    const float* Wo = (const float*)d_in[9];
    const float* bo = (const float*)d_in[10];
    float* out = (float*)d_out;

    pe_add_kernel<<<NROWS, 256>>>(x, rel, alpha);
    wsplit_kernel<<<4096, 256>>>(Wq, Wk, Wv, Wo);
    gemm_qkv_kernel<<<dim3(D_MODEL / 128, NROWS / 128, 3), 256>>>(bq, bk, bv);
    flash_kernel<<<dim3(SEQ / 64, BHN), 256>>>();
    gemm_out_kernel<<<dim3(D_MODEL / 128, NROWS / 128), 256>>>(bo, out);
}